// round 3
// baseline (speedup 1.0000x reference)
#include <cuda_runtime.h>
#include <cstdint>

#define NMAX 50000
#define EMAX 800000
#define F 144

typedef unsigned long long ull;

// ---- scratch (no allocations allowed; __device__ globals) ----
__device__ int   g_deg[NMAX];
__device__ float g_dinv[NMAX];
__device__ int   g_rowptr[NMAX + 1];
__device__ int   g_cursor[NMAX];
__device__ int   g_ccol[EMAX];
__device__ float g_cval[EMAX];
__device__ float g_tx1[(size_t)NMAX * F];
__device__ float g_tx2[(size_t)NMAX * F];

// ---------------------------------------------------------------------------
// 1) zero degree counters
// ---------------------------------------------------------------------------
__global__ void zero_deg_kernel(int n) {
    int i = blockIdx.x * blockDim.x + threadIdx.x;
    if (i < n) g_deg[i] = 0;
}

// ---------------------------------------------------------------------------
// 2) degree histogram (self-loops masked out)
// ---------------------------------------------------------------------------
__global__ void hist_kernel(const int* __restrict__ row, const int* __restrict__ col, int e) {
    int i = blockIdx.x * blockDim.x + threadIdx.x;
    if (i < e) {
        int r = row[i];
        if (r != col[i]) atomicAdd(&g_deg[r], 1);
    }
}

// ---------------------------------------------------------------------------
// 3) single-block scan: rowptr (exclusive prefix of deg), cursor, dinv
// ---------------------------------------------------------------------------
__global__ void scan_kernel(int n) {
    __shared__ int sm[1024];
    int tid = threadIdx.x;
    int chunk = (n + 1023) >> 10;
    int start = tid * chunk;
    int end = start + chunk; if (end > n) end = n;

    int s = 0;
    for (int i = start; i < end; ++i) s += g_deg[i];
    sm[tid] = s;
    __syncthreads();

    // Hillis-Steele inclusive scan
    for (int off = 1; off < 1024; off <<= 1) {
        int v = (tid >= off) ? sm[tid - off] : 0;
        __syncthreads();
        sm[tid] += v;
        __syncthreads();
    }

    int run = (tid > 0) ? sm[tid - 1] : 0;
    for (int i = start; i < end; ++i) {
        g_rowptr[i] = run;
        g_cursor[i] = run;
        int d = g_deg[i];
        g_dinv[i] = (d > 0) ? rsqrtf((float)d) : 0.0f;
        run += d;
    }
    if (end == n && start < n) g_rowptr[n] = run;
}

// ---------------------------------------------------------------------------
// 4) scatter edges into CSR with normalized Laplacian values
// ---------------------------------------------------------------------------
__global__ void scatter_kernel(const int* __restrict__ row, const int* __restrict__ col,
                               const float* __restrict__ w, int e) {
    int i = blockIdx.x * blockDim.x + threadIdx.x;
    if (i < e) {
        int r = row[i];
        int c = col[i];
        if (r != c) {
            int p = atomicAdd(&g_cursor[r], 1);
            g_ccol[p] = c;
            g_cval[p] = -g_dinv[r] * w[i] * g_dinv[c];
        }
    }
}

// ---------------------------------------------------------------------------
// 5) SpMM: pass 0:  tx1 = L @ x
//          pass 1:  tx2 = 2 * (L @ tx1) - x
//    one block per row, one thread per feature (coalesced gather of x[col])
// ---------------------------------------------------------------------------
__global__ void spmm_kernel(const float* __restrict__ xin, int n, int pass) {
    int r = blockIdx.x;
    int f = threadIdx.x;
    if (f >= F) return;

    const float* __restrict__ src = (pass == 0) ? xin : g_tx1;
    float* __restrict__ dst = (pass == 0) ? g_tx1 : g_tx2;

    int s = g_rowptr[r];
    int e = g_rowptr[r + 1];

    float acc = 0.0f;
    int i = s;
    // unroll by 4 for MLP
    for (; i + 3 < e; i += 4) {
        int c0 = g_ccol[i + 0], c1 = g_ccol[i + 1], c2 = g_ccol[i + 2], c3 = g_ccol[i + 3];
        float w0 = g_cval[i + 0], w1 = g_cval[i + 1], w2 = g_cval[i + 2], w3 = g_cval[i + 3];
        float v0 = __ldg(&src[(size_t)c0 * F + f]);
        float v1 = __ldg(&src[(size_t)c1 * F + f]);
        float v2 = __ldg(&src[(size_t)c2 * F + f]);
        float v3 = __ldg(&src[(size_t)c3 * F + f]);
        acc += w0 * v0; acc += w1 * v1; acc += w2 * v2; acc += w3 * v3;
    }
    for (; i < e; ++i) {
        int c = g_ccol[i];
        acc += g_cval[i] * __ldg(&src[(size_t)c * F + f]);
    }

    size_t o = (size_t)r * F + f;
    if (pass == 0) {
        dst[o] = acc;
    } else {
        dst[o] = 2.0f * acc - xin[o];
    }
}

// ---------------------------------------------------------------------------
// 6) fused GEMM: out[N,144] = x@W0 + tx1@W1 + tx2@W2 + bias
//    Tiles: BM=64, BN=144 (full width), BK=24, 384 threads, 4x6 micro-tile.
//    Packed fp32x2 FMA (fma.rn.f32x2) doubles fp32 throughput.
// ---------------------------------------------------------------------------
#define BM 64
#define BN 144
#define BK 24
#define GT 384

__device__ __forceinline__ ull fdup(float v) {
    unsigned u = __float_as_uint(v);
    return (ull)u | ((ull)u << 32);
}
__device__ __forceinline__ void ffma2(ull& d, ull a, ull b) {
    asm("fma.rn.f32x2 %0, %1, %2, %0;" : "+l"(d) : "l"(a), "l"(b));
}

__global__ __launch_bounds__(GT) void gemm_kernel(const float* __restrict__ x,
                                                  const float* __restrict__ wgt,
                                                  const float* __restrict__ bias,
                                                  float* __restrict__ out, int n) {
    __shared__ __align__(16) ull   As[BK][BM];   // value duplicated into both 32-bit halves
    __shared__ __align__(16) float Bs[BK][BN];

    int tid = threadIdx.x;
    int m0 = blockIdx.x * BM;
    int cg = tid % 24;   // column group: cols cg*6 .. cg*6+5
    int rg = tid / 24;   // row group:    rows rg*4 .. rg*4+3

    ull acc[4][3];
#pragma unroll
    for (int r = 0; r < 4; ++r)
#pragma unroll
        for (int p = 0; p < 3; ++p) acc[r][p] = 0ull;

    for (int kt = 0; kt < 18; ++kt) {
        int kbase = kt * BK;          // 0..431
        int s = kbase / F;            // which source / weight slab
        int kl = kbase % F;           // column offset within source
        const float* __restrict__ A = (s == 0) ? x : ((s == 1) ? g_tx1 : g_tx2);

        // load A tile (64 x 24) -> duplicated pairs
#pragma unroll
        for (int p = 0; p < 4; ++p) {
            int idx = p * GT + tid;
            int kk = idx % BK, m = idx / BK;
            int gm = m0 + m;
            float v = (gm < n) ? __ldg(&A[(size_t)gm * F + kl + kk]) : 0.0f;
            As[kk][m] = fdup(v);
        }
        // load B tile (24 x 144), coalesced
        const float* __restrict__ W = wgt + (size_t)s * F * F + (size_t)kl * F;
#pragma unroll
        for (int p = 0; p < 9; ++p) {
            int idx = p * GT + tid;
            int kk = idx / BN, j = idx % BN;
            Bs[kk][j] = __ldg(&W[kk * F + j]);
        }
        __syncthreads();

#pragma unroll
        for (int kk = 0; kk < BK; ++kk) {
            ulonglong2 a01 = *reinterpret_cast<const ulonglong2*>(&As[kk][rg * 4]);
            ulonglong2 a23 = *reinterpret_cast<const ulonglong2*>(&As[kk][rg * 4 + 2]);
            ull aa0 = a01.x, aa1 = a01.y, aa2 = a23.x, aa3 = a23.y;
            const float* bp = &Bs[kk][cg * 6];
            ull b0 = *reinterpret_cast<const ull*>(bp);
            ull b1 = *reinterpret_cast<const ull*>(bp + 2);
            ull b2 = *reinterpret_cast<const ull*>(bp + 4);
            ffma2(acc[0][0], aa0, b0); ffma2(acc[0][1], aa0, b1); ffma2(acc[0][2], aa0, b2);
            ffma2(acc[1][0], aa1, b0); ffma2(acc[1][1], aa1, b1); ffma2(acc[1][2], aa1, b2);
            ffma2(acc[2][0], aa2, b0); ffma2(acc[2][1], aa2, b1); ffma2(acc[2][2], aa2, b2);
            ffma2(acc[3][0], aa3, b0); ffma2(acc[3][1], aa3, b1); ffma2(acc[3][2], aa3, b2);
        }
        __syncthreads();
    }

    // epilogue: + bias, write
    float bl[6];
#pragma unroll
    for (int p = 0; p < 6; ++p) bl[p] = __ldg(&bias[cg * 6 + p]);

#pragma unroll
    for (int r = 0; r < 4; ++r) {
        int gm = m0 + rg * 4 + r;
        if (gm < n) {
            float* o = out + (size_t)gm * F + cg * 6;
#pragma unroll
            for (int p = 0; p < 3; ++p) {
                float lo = __uint_as_float((unsigned)(acc[r][p] & 0xffffffffu));
                float hi = __uint_as_float((unsigned)(acc[r][p] >> 32));
                float2 v2 = make_float2(lo + bl[2 * p], hi + bl[2 * p + 1]);
                *reinterpret_cast<float2*>(o + 2 * p) = v2;
            }
        }
    }
}

// ---------------------------------------------------------------------------
// launcher
// ---------------------------------------------------------------------------
extern "C" void kernel_launch(void* const* d_in, const int* in_sizes, int n_in,
                              void* d_out, int out_size) {
    const float* x    = (const float*)d_in[0];   // [N, 144]
    const int*   ei   = (const int*)d_in[1];     // [2, E]
    const float* ew   = (const float*)d_in[2];   // [E]
    const float* wgt  = (const float*)d_in[3];   // [3, 144, 144]
    const float* bias = (const float*)d_in[4];   // [144]
    float* out = (float*)d_out;

    int n = in_sizes[0] / F;
    int e = in_sizes[2];
    const int* row = ei;
    const int* col = ei + e;

    zero_deg_kernel<<<(n + 255) / 256, 256>>>(n);
    hist_kernel<<<(e + 255) / 256, 256>>>(row, col, e);
    scan_kernel<<<1, 1024>>>(n);
    scatter_kernel<<<(e + 255) / 256, 256>>>(row, col, ew, e);
    spmm_kernel<<<n, 160>>>(x, n, 0);   // tx1 = L x
    spmm_kernel<<<n, 160>>>(x, n, 1);   // tx2 = 2 L tx1 - x
    gemm_kernel<<<(n + BM - 1) / BM, GT>>>(x, wgt, bias, out, n);
}

// round 6
// speedup vs baseline: 1.9377x; 1.9377x over previous
#include <cuda_runtime.h>
#include <cstdint>

#define NMAX 50000
#define EMAX 800000
#define F 144

typedef unsigned long long ull;

// ---- scratch (no allocations allowed; __device__ globals) ----
__device__ int    g_deg[NMAX];
__device__ float  g_dinv[NMAX];
__device__ int    g_rowptr[NMAX + 1];
__device__ int    g_cursor[NMAX];
__device__ int2   g_edge[EMAX];                 // {col, valbits}
__device__ int    g_bsum[128];
__device__ int    g_boff[128];
__device__ float4 g_tx1[(size_t)NMAX * 36];
__device__ float4 g_tx2[(size_t)NMAX * 36];

// ---------------------------------------------------------------------------
// graph build
// ---------------------------------------------------------------------------
__global__ void zero_deg_kernel(int n) {
    int i = blockIdx.x * blockDim.x + threadIdx.x;
    if (i < n) g_deg[i] = 0;
}

__global__ void hist4_kernel(const int* __restrict__ row, const int* __restrict__ col, int e) {
    int i = (blockIdx.x * blockDim.x + threadIdx.x) * 4;
    if (i + 4 <= e) {
        int4 r = *reinterpret_cast<const int4*>(row + i);
        int4 c = *reinterpret_cast<const int4*>(col + i);
        if (r.x != c.x) atomicAdd(&g_deg[r.x], 1);
        if (r.y != c.y) atomicAdd(&g_deg[r.y], 1);
        if (r.z != c.z) atomicAdd(&g_deg[r.z], 1);
        if (r.w != c.w) atomicAdd(&g_deg[r.w], 1);
    } else {
        for (; i < e; ++i) {
            int r = row[i];
            if (r != col[i]) atomicAdd(&g_deg[r], 1);
        }
    }
}

__global__ void scanA_kernel(int n) {   // per-block reduce (coalesced)
    __shared__ int sm[512];
    int t = threadIdx.x, i = blockIdx.x * 512 + t;
    sm[t] = (i < n) ? g_deg[i] : 0;
    __syncthreads();
    for (int off = 256; off > 0; off >>= 1) {
        if (t < off) sm[t] += sm[t + off];
        __syncthreads();
    }
    if (t == 0) g_bsum[blockIdx.x] = sm[0];
}

__global__ void scanB_kernel(int nb) {  // single block scan of <=128 sums
    __shared__ int sm[128];
    int t = threadIdx.x;
    sm[t] = (t < nb) ? g_bsum[t] : 0;
    __syncthreads();
    for (int off = 1; off < 128; off <<= 1) {
        int v = (t >= off) ? sm[t - off] : 0;
        __syncthreads();
        sm[t] += v;
        __syncthreads();
    }
    if (t < nb) g_boff[t] = t ? sm[t - 1] : 0;
}

__global__ void scanC_kernel(int n) {   // per-block local scan + offset
    __shared__ int sm[512];
    int t = threadIdx.x, b = blockIdx.x, i = b * 512 + t;
    int d = (i < n) ? g_deg[i] : 0;
    sm[t] = d;
    __syncthreads();
    for (int off = 1; off < 512; off <<= 1) {
        int v = (t >= off) ? sm[t - off] : 0;
        __syncthreads();
        sm[t] += v;
        __syncthreads();
    }
    if (i < n) {
        int excl = g_boff[b] + sm[t] - d;
        g_rowptr[i] = excl;
        g_cursor[i] = excl;
        g_dinv[i] = (d > 0) ? rsqrtf((float)d) : 0.0f;
        if (i == n - 1) g_rowptr[n] = excl + d;
    }
}

__global__ void scatter2_kernel(const int* __restrict__ row, const int* __restrict__ col,
                                const float* __restrict__ w, int e) {
    int i = (blockIdx.x * blockDim.x + threadIdx.x) * 2;
    if (i + 2 <= e) {
        int2 r = *reinterpret_cast<const int2*>(row + i);
        int2 c = *reinterpret_cast<const int2*>(col + i);
        float2 ww = *reinterpret_cast<const float2*>(w + i);
        if (r.x != c.x) {
            int p = atomicAdd(&g_cursor[r.x], 1);
            g_edge[p] = make_int2(c.x, __float_as_int(-g_dinv[r.x] * ww.x * g_dinv[c.x]));
        }
        if (r.y != c.y) {
            int p = atomicAdd(&g_cursor[r.y], 1);
            g_edge[p] = make_int2(c.y, __float_as_int(-g_dinv[r.y] * ww.y * g_dinv[c.y]));
        }
    } else if (i < e) {
        int r = row[i], c = col[i];
        if (r != c) {
            int p = atomicAdd(&g_cursor[r], 1);
            g_edge[p] = make_int2(c, __float_as_int(-g_dinv[r] * w[i] * g_dinv[c]));
        }
    }
}

// ---------------------------------------------------------------------------
// SpMM: pass 0: tx1 = L @ x      pass 1: tx2 = 2*(L @ tx1) - x
// block (36,8): 36 float4 lanes per row, 8 rows per block
// ---------------------------------------------------------------------------
__global__ void spmm_kernel(const float4* __restrict__ x4, int n, int pass) {
    int r = blockIdx.x * 8 + threadIdx.y;
    if (r >= n) return;
    int lane = threadIdx.x;  // 0..35

    const float4* __restrict__ src = pass ? (const float4*)g_tx1 : x4;

    int s = g_rowptr[r];
    int e = g_rowptr[r + 1];

    float4 acc = make_float4(0.f, 0.f, 0.f, 0.f);
    int i = s;
    for (; i + 4 <= e; i += 4) {
        int2 e0 = __ldg(&g_edge[i + 0]);
        int2 e1 = __ldg(&g_edge[i + 1]);
        int2 e2 = __ldg(&g_edge[i + 2]);
        int2 e3 = __ldg(&g_edge[i + 3]);
        float4 v0 = __ldg(&src[(size_t)e0.x * 36 + lane]);
        float4 v1 = __ldg(&src[(size_t)e1.x * 36 + lane]);
        float4 v2 = __ldg(&src[(size_t)e2.x * 36 + lane]);
        float4 v3 = __ldg(&src[(size_t)e3.x * 36 + lane]);
        float w0 = __int_as_float(e0.y), w1 = __int_as_float(e1.y);
        float w2 = __int_as_float(e2.y), w3 = __int_as_float(e3.y);
        acc.x = fmaf(w0, v0.x, acc.x); acc.y = fmaf(w0, v0.y, acc.y);
        acc.z = fmaf(w0, v0.z, acc.z); acc.w = fmaf(w0, v0.w, acc.w);
        acc.x = fmaf(w1, v1.x, acc.x); acc.y = fmaf(w1, v1.y, acc.y);
        acc.z = fmaf(w1, v1.z, acc.z); acc.w = fmaf(w1, v1.w, acc.w);
        acc.x = fmaf(w2, v2.x, acc.x); acc.y = fmaf(w2, v2.y, acc.y);
        acc.z = fmaf(w2, v2.z, acc.z); acc.w = fmaf(w2, v2.w, acc.w);
        acc.x = fmaf(w3, v3.x, acc.x); acc.y = fmaf(w3, v3.y, acc.y);
        acc.z = fmaf(w3, v3.z, acc.z); acc.w = fmaf(w3, v3.w, acc.w);
    }
    for (; i < e; ++i) {
        int2 ee = __ldg(&g_edge[i]);
        float4 v = __ldg(&src[(size_t)ee.x * 36 + lane]);
        float w = __int_as_float(ee.y);
        acc.x = fmaf(w, v.x, acc.x); acc.y = fmaf(w, v.y, acc.y);
        acc.z = fmaf(w, v.z, acc.z); acc.w = fmaf(w, v.w, acc.w);
    }

    size_t o = (size_t)r * 36 + lane;
    if (pass) {
        float4 xo = __ldg(&x4[o]);
        acc.x = 2.f * acc.x - xo.x; acc.y = 2.f * acc.y - xo.y;
        acc.z = 2.f * acc.z - xo.z; acc.w = 2.f * acc.w - xo.w;
        g_tx2[o] = acc;
    } else {
        g_tx1[o] = acc;
    }
}

// ---------------------------------------------------------------------------
// fused GEMM: out[N,144] = x@W0 + tx1@W1 + tx2@W2 + bias
// BM=128, BN=144, BK=24, 384 threads, 4x12 micro-tile, packed f32x2 FMA.
// As: [24][130] ull (k-major rows, value duplicated; pad kills bank conflicts)
// Bs: [24][148] float (+2 word shift at col 96 -> 12 lane groups, 12 banks)
// Register double-buffer of both tiles hides LDG latency behind the kk loop.
// ---------------------------------------------------------------------------
#define BM 128
#define GT 384

__device__ __forceinline__ ull fdup(float v) {
    unsigned u = __float_as_uint(v);
    return (ull)u | ((ull)u << 32);
}
__device__ __forceinline__ void ffma2(ull& d, ull a, ull b) {
    asm("fma.rn.f32x2 %0, %1, %2, %0;" : "+l"(d) : "l"(a), "l"(b));
}

__global__ __launch_bounds__(GT) void gemm_kernel(const float* __restrict__ x,
                                                  const float* __restrict__ wgt,
                                                  const float* __restrict__ bias,
                                                  float* __restrict__ out, int n) {
    __shared__ __align__(16) ull   As[24 * 130];
    __shared__ __align__(16) float Bs[24 * 148];

    int tid = threadIdx.x;
    int m0 = blockIdx.x * BM;
    int cg = tid % 12;            // column group: 12 logical cols
    int rg = tid / 12;            // row group: 4 rows  (0..31)
    int colS = 12 * cg + ((cg >= 8) ? 2 : 0);  // smem phys col base
    int colG = 12 * cg;                        // gmem col base

    // A load mapping: 2 float4 per thread covering 128 x 24 tile
    int qa0 = tid % 6,         ma0 = tid / 6;
    int qa1 = (GT + tid) % 6,  ma1 = (GT + tid) / 6;
    // B phys store offsets (9 floats per thread, tile is contiguous 3456 floats)
    int physb[9];
#pragma unroll
    for (int p = 0; p < 9; ++p) {
        int idx = p * GT + tid;
        int j = idx % 144, kk = idx / 144;
        physb[p] = kk * 148 + j + ((j >= 96) ? 2 : 0);
    }

    ull acc[4][6];
#pragma unroll
    for (int r = 0; r < 4; ++r)
#pragma unroll
        for (int p = 0; p < 6; ++p) acc[r][p] = 0ull;

    const float* t1 = (const float*)g_tx1;
    const float* t2 = (const float*)g_tx2;

    float4 av0, av1;
    float bv[9];

    // prefetch kt = 0 (slab 0, kl = 0)
    {
        int gm0 = m0 + ma0, gm1 = m0 + ma1;
        av0 = (gm0 < n) ? *reinterpret_cast<const float4*>(x + (size_t)gm0 * 144 + 4 * qa0)
                        : make_float4(0.f, 0.f, 0.f, 0.f);
        av1 = (gm1 < n) ? *reinterpret_cast<const float4*>(x + (size_t)gm1 * 144 + 4 * qa1)
                        : make_float4(0.f, 0.f, 0.f, 0.f);
#pragma unroll
        for (int p = 0; p < 9; ++p) bv[p] = __ldg(&wgt[p * GT + tid]);
    }

    for (int kt = 0; kt < 18; ++kt) {
        // store staged tile to smem
        As[(4 * qa0 + 0) * 130 + ma0] = fdup(av0.x);
        As[(4 * qa0 + 1) * 130 + ma0] = fdup(av0.y);
        As[(4 * qa0 + 2) * 130 + ma0] = fdup(av0.z);
        As[(4 * qa0 + 3) * 130 + ma0] = fdup(av0.w);
        As[(4 * qa1 + 0) * 130 + ma1] = fdup(av1.x);
        As[(4 * qa1 + 1) * 130 + ma1] = fdup(av1.y);
        As[(4 * qa1 + 2) * 130 + ma1] = fdup(av1.z);
        As[(4 * qa1 + 3) * 130 + ma1] = fdup(av1.w);
#pragma unroll
        for (int p = 0; p < 9; ++p) Bs[physb[p]] = bv[p];
        __syncthreads();

        // prefetch next tile into registers (overlaps with compute below)
        if (kt < 17) {
            int kn = kt + 1;
            int s = kn / 6;
            int kl = (kn % 6) * 24;
            const float* A = (s == 0) ? x : ((s == 1) ? t1 : t2);
            int gm0 = m0 + ma0, gm1 = m0 + ma1;
            av0 = (gm0 < n) ? *reinterpret_cast<const float4*>(A + (size_t)gm0 * 144 + kl + 4 * qa0)
                            : make_float4(0.f, 0.f, 0.f, 0.f);
            av1 = (gm1 < n) ? *reinterpret_cast<const float4*>(A + (size_t)gm1 * 144 + kl + 4 * qa1)
                            : make_float4(0.f, 0.f, 0.f, 0.f);
            const float* Wt = wgt + (size_t)s * 20736 + (size_t)kl * 144;
#pragma unroll
            for (int p = 0; p < 9; ++p) bv[p] = __ldg(&Wt[p * GT + tid]);
        }

#pragma unroll
        for (int kk = 0; kk < 24; ++kk) {
            const ull* ar = &As[kk * 130 + rg * 4];
            ulonglong2 A01 = *reinterpret_cast<const ulonglong2*>(ar);
            ulonglong2 A23 = *reinterpret_cast<const ulonglong2*>(ar + 2);
            ull a0 = A01.x, a1 = A01.y, a2 = A23.x, a3 = A23.y;
            const float* bp = &Bs[kk * 148 + colS];
            ull b0 = *reinterpret_cast<const ull*>(bp);
            ull b1 = *reinterpret_cast<const ull*>(bp + 2);
            ull b2 = *reinterpret_cast<const ull*>(bp + 4);
            ull b3 = *reinterpret_cast<const ull*>(bp + 6);
            ull b4 = *reinterpret_cast<const ull*>(bp + 8);
            ull b5 = *reinterpret_cast<const ull*>(bp + 10);
            ffma2(acc[0][0], a0, b0); ffma2(acc[0][1], a0, b1); ffma2(acc[0][2], a0, b2);
            ffma2(acc[0][3], a0, b3); ffma2(acc[0][4], a0, b4); ffma2(acc[0][5], a0, b5);
            ffma2(acc[1][0], a1, b0); ffma2(acc[1][1], a1, b1); ffma2(acc[1][2], a1, b2);
            ffma2(acc[1][3], a1, b3); ffma2(acc[1][4], a1, b4); ffma2(acc[1][5], a1, b5);
            ffma2(acc[2][0], a2, b0); ffma2(acc[2][1], a2, b1); ffma2(acc[2][2], a2, b2);
            ffma2(acc[2][3], a2, b3); ffma2(acc[2][4], a2, b4); ffma2(acc[2][5], a2, b5);
            ffma2(acc[3][0], a3, b0); ffma2(acc[3][1], a3, b1); ffma2(acc[3][2], a3, b2);
            ffma2(acc[3][3], a3, b3); ffma2(acc[3][4], a3, b4); ffma2(acc[3][5], a3, b5);
        }
        __syncthreads();
    }

    // epilogue: + bias, vectorized float4 stores
    float bl[12];
#pragma unroll
    for (int t = 0; t < 12; ++t) bl[t] = __ldg(&bias[colG + t]);

#pragma unroll
    for (int r = 0; r < 4; ++r) {
        int gm = m0 + rg * 4 + r;
        if (gm < n) {
            float* o = out + (size_t)gm * 144 + colG;
#pragma unroll
            for (int q = 0; q < 3; ++q) {
                ull p0 = acc[r][2 * q], p1 = acc[r][2 * q + 1];
                float4 v;
                v.x = __uint_as_float((unsigned)(p0 & 0xffffffffu)) + bl[4 * q + 0];
                v.y = __uint_as_float((unsigned)(p0 >> 32))         + bl[4 * q + 1];
                v.z = __uint_as_float((unsigned)(p1 & 0xffffffffu)) + bl[4 * q + 2];
                v.w = __uint_as_float((unsigned)(p1 >> 32))         + bl[4 * q + 3];
                *reinterpret_cast<float4*>(o + 4 * q) = v;
            }
        }
    }
}

// ---------------------------------------------------------------------------
// launcher
// ---------------------------------------------------------------------------
extern "C" void kernel_launch(void* const* d_in, const int* in_sizes, int n_in,
                              void* d_out, int out_size) {
    const float* x    = (const float*)d_in[0];   // [N, 144]
    const int*   ei   = (const int*)d_in[1];     // [2, E]
    const float* ew   = (const float*)d_in[2];   // [E]
    const float* wgt  = (const float*)d_in[3];   // [3, 144, 144]
    const float* bias = (const float*)d_in[4];   // [144]
    float* out = (float*)d_out;

    int n = in_sizes[0] / F;
    int e = in_sizes[2];
    const int* row = ei;
    const int* col = ei + e;
    int nb = (n + 511) / 512;

    zero_deg_kernel<<<(n + 255) / 256, 256>>>(n);
    hist4_kernel<<<((e + 3) / 4 + 255) / 256, 256>>>(row, col, e);
    scanA_kernel<<<nb, 512>>>(n);
    scanB_kernel<<<1, 128>>>(nb);
    scanC_kernel<<<nb, 512>>>(n);
    scatter2_kernel<<<((e + 1) / 2 + 255) / 256, 256>>>(row, col, ew, e);

    dim3 sb(36, 8);
    spmm_kernel<<<(n + 7) / 8, sb>>>((const float4*)x, n, 0);   // tx1 = L x
    spmm_kernel<<<(n + 7) / 8, sb>>>((const float4*)x, n, 1);   // tx2 = 2 L tx1 - x

    gemm_kernel<<<(n + BM - 1) / BM, GT>>>(x, wgt, bias, out, n);
}